// round 1
// baseline (speedup 1.0000x reference)
#include <cuda_runtime.h>
#include <cuda_fp16.h>
#include <cstdint>
#include <math.h>

// ---------------- problem constants ----------------
// feature: [8, 1024, 64, 64] f32 ; conv_w: [1024, 1049] ; conv_b: [1024]
// out: [8, 1024, 64, 64] f32
// cat channels: 0..1023 = feature, 1024..1048 = corr (j = cc*5 + r), pad to 1056.

#define B_      8
#define C_      1024
#define HW_     4096
#define OC_     1024
#define KTOT    1056      // padded K (33 * 32)
#define KREAL   1049

// ---------------- scratch (__device__ globals; no allocation) ----------------
__device__ __half g_Wh[OC_ * KTOT];                 // fp16 weights, zero-padded
__device__ float  g_sspart[2 * B_ * HW_];           // per-group sum of squares
__device__ float  g_inv[B_ * HW_];                  // 1/max(||f||,eps)
__device__ float  g_accpart[2 * B_ * 25 * HW_];     // per-group raw corr dots
__device__ float  g_corr[B_ * 32 * HW_];            // normalized corr, planes 25..31 = 0

// ============================================================
// K0: convert conv_w -> fp16, pad K to 1056
// ============================================================
__global__ void convW_kernel(const float* __restrict__ w) {
    int idx = blockIdx.x * 256 + threadIdx.x;
    if (idx >= OC_ * KTOT) return;
    int o = idx / KTOT, k = idx - o * KTOT;
    float v = (k < KREAL) ? w[o * KREAL + k] : 0.0f;
    g_Wh[idx] = __float2half(v);
}

// ============================================================
// K1: correlation partial sums + per-pixel sumsq.
// Tile: 32x8 pixels per block, halo tile 12 rows x 40 cols (x aligned to 16B).
// Channels split into 2 groups of 512 (grid.z = b*2+g) for occupancy.
// 4 channels per iteration, double-buffered with cp.async (16B chunks).
// ============================================================
__global__ void corr_kernel(const float* __restrict__ feat) {
    __shared__ float tile[2][4][12 * 40];   // 2 bufs x 4 ch x 480 floats = 15360 B

    const int tid = threadIdx.x;
    const int tx = tid & 31, ty = tid >> 5;
    const int x0 = blockIdx.x * 32, y0 = blockIdx.y * 8;
    const int b = blockIdx.z >> 1, g = blockIdx.z & 1;
    const float* fb = feat + (size_t)b * C_ * HW_;
    const int cbase = g * 512;

    float acc[25];
#pragma unroll
    for (int j = 0; j < 25; j++) acc[j] = 0.0f;
    float ss = 0.0f;

    auto load4 = [&](int c0, int buf) {
        // 480 16B-chunks: 4 ch x 12 rows x 10 chunks
#pragma unroll 2
        for (int u = tid; u < 480; u += 256) {
            int cc = u / 120, pos = u - cc * 120;
            int j = pos / 10, i = pos - j * 10;
            int gy = y0 - 2 + j;
            int gx0 = x0 - 4 + i * 4;
            bool valid = ((unsigned)gy < 64u) && ((unsigned)gx0 < 64u);
            const float* src = fb + (size_t)(c0 + cc) * HW_ + (valid ? (gy * 64 + gx0) : 0);
            unsigned dst = (unsigned)__cvta_generic_to_shared(&tile[buf][cc][j * 40 + i * 4]);
            int sz = valid ? 16 : 0;
            asm volatile("cp.async.ca.shared.global [%0], [%1], 16, %2;\n"
                         :: "r"(dst), "l"(src), "r"(sz));
        }
    };

    load4(cbase, 0);
    asm volatile("cp.async.commit_group;\n");

    for (int it = 0; it < 128; ++it) {
        if (it < 127) {
            load4(cbase + (it + 1) * 4, (it + 1) & 1);
            asm volatile("cp.async.commit_group;\n");
            asm volatile("cp.async.wait_group 1;\n");
        } else {
            asm volatile("cp.async.wait_group 0;\n");
        }
        __syncthreads();
        const int cb = it & 1;
#pragma unroll
        for (int q = 0; q < 4; q++) {
            const float* tq = &tile[cb][q][0];
            float cen = tq[(ty + 2) * 40 + (tx + 4)];
            ss += cen * cen;
#pragma unroll
            for (int cc = 0; cc < 5; cc++) {
#pragma unroll
                for (int r = 0; r < 5; r++) {
                    acc[cc * 5 + r] += tq[(ty + r) * 40 + (tx + cc + 2)] * cen;
                }
            }
        }
        __syncthreads();
    }

    int p = (y0 + ty) * 64 + (x0 + tx);
    g_sspart[(g * B_ + b) * HW_ + p] = ss;
#pragma unroll
    for (int j = 0; j < 25; j++)
        g_accpart[((g * B_ + b) * 25 + j) * HW_ + p] = acc[j];
}

// ============================================================
// K2: inv = 1 / max(sqrt(ss0+ss1), eps)
// ============================================================
__global__ void inv_kernel() {
    int idx = blockIdx.x * 256 + threadIdx.x;     // B_*HW_
    if (idx >= B_ * HW_) return;
    float ssv = g_sspart[idx] + g_sspart[B_ * HW_ + idx];
    float n = sqrtf(ssv);
    g_inv[idx] = 1.0f / fmaxf(n, 1e-12f);
}

// ============================================================
// K3: corr[b][j][p] = (acc0+acc1) * inv[p] * inv[tap], planes 25..31 = 0
// ============================================================
__global__ void combine_kernel() {
    int idx = blockIdx.x * 256 + threadIdx.x;     // B_*32*HW_
    if (idx >= B_ * 32 * HW_) return;
    int p = idx & (HW_ - 1);
    int j = (idx >> 12) & 31;
    int b = idx >> 17;
    float v = 0.0f;
    if (j < 25) {
        int y = p >> 6, x = p & 63;
        int ccs = j / 5, r = j - ccs * 5;
        int tyy = y + r - 2, txx = x + ccs - 2;
        if ((unsigned)tyy < 64u && (unsigned)txx < 64u) {
            float a = g_accpart[(b * 25 + j) * HW_ + p] +
                      g_accpart[((B_ + b) * 25 + j) * HW_ + p];
            v = a * g_inv[b * HW_ + p] * g_inv[b * HW_ + tyy * 64 + txx];
        }
    }
    g_corr[idx] = v;
}

// ============================================================
// K4: GEMM  out[b,o,p] = relu( sum_k Wh[o,k]*Acat[p,k] + bias[o] )
// CTA tile 128p x 128o x 32k, 256 threads (8 warps: 4 along m, 2 along n).
// A tile: feature/corr fp32 -> LDG regs -> fp16 -> STS (layout [k][m], ldmatrix.trans)
// B tile: g_Wh fp16 via cp.async (layout [n][k], ldmatrix)
// ============================================================
__global__ __launch_bounds__(256) void gemm_kernel(const float* __restrict__ feat,
                                                   const float* __restrict__ bias,
                                                   float* __restrict__ out) {
    __shared__ __align__(16) unsigned char SM[38912];
    __half* As[2] = { (__half*)SM, (__half*)(SM + 8704) };               // [32][136]
    __half* Bs[2] = { (__half*)(SM + 17408), (__half*)(SM + 27648) };    // [128][40]
    float* Ep = (float*)SM;                                              // [128][33] epilogue

    const int tid = threadIdx.x;
    const int lane = tid & 31, wid = tid >> 5;
    const int wm = wid & 3, wn = wid >> 2;
    const int o0 = blockIdx.x * 128;
    const int p0 = blockIdx.y * 128;
    const int b  = blockIdx.z;

    const int arow = tid >> 3;            // k-row within tile (0..31)
    const int acol = (tid & 7) * 16;      // p offset (16 floats per thread)

    float accv[2][8][4];
#pragma unroll
    for (int i = 0; i < 2; i++)
#pragma unroll
        for (int j = 0; j < 8; j++)
#pragma unroll
            for (int e = 0; e < 4; e++) accv[i][j][e] = 0.0f;

    float areg[16];

    auto loadA = [&](int kt) {
        int k = kt * 32 + arow;
        const float* src;
        if (k < C_) src = feat + (((size_t)(b * C_ + k)) << 12) + p0 + acol;
        else        src = g_corr + (((size_t)(b * 32 + (k - C_))) << 12) + p0 + acol;
#pragma unroll
        for (int i = 0; i < 4; i++) {
            float4 v = *(const float4*)(src + i * 4);
            areg[i * 4 + 0] = v.x; areg[i * 4 + 1] = v.y;
            areg[i * 4 + 2] = v.z; areg[i * 4 + 3] = v.w;
        }
    };
    auto stsA = [&](int buf) {
        __half h[16];
#pragma unroll
        for (int i = 0; i < 16; i++) h[i] = __float2half(areg[i]);
        __half* d = As[buf] + arow * 136 + acol;
        *(uint4*)(d)     = *(uint4*)(h);
        *(uint4*)(d + 8) = *(uint4*)(h + 8);
    };
    auto loadB = [&](int kt, int buf) {
        int k0 = kt * 32;
#pragma unroll
        for (int s = 0; s < 2; s++) {
            int ch = tid + s * 256;
            int orow = ch >> 2, q = ch & 3;
            const __half* src = g_Wh + (size_t)(o0 + orow) * KTOT + k0 + q * 8;
            unsigned dst = (unsigned)__cvta_generic_to_shared(Bs[buf] + orow * 40 + q * 8);
            asm volatile("cp.async.ca.shared.global [%0], [%1], 16;\n" :: "r"(dst), "l"(src));
        }
    };
    auto compute = [&](int buf) {
#pragma unroll
        for (int ks = 0; ks < 2; ks++) {
            const int kb = ks * 16;
            unsigned a[2][4];
#pragma unroll
            for (int fm = 0; fm < 2; fm++) {
                int m0 = wm * 32 + fm * 16;
                int kk = kb + ((lane >> 4) & 1) * 8 + (lane & 7);
                int mm = m0 + ((lane >> 3) & 1) * 8;
                unsigned addr = (unsigned)__cvta_generic_to_shared(As[buf] + kk * 136 + mm);
                asm volatile("ldmatrix.sync.aligned.m8n8.x4.trans.shared.b16 {%0,%1,%2,%3}, [%4];\n"
                             : "=r"(a[fm][0]), "=r"(a[fm][1]), "=r"(a[fm][2]), "=r"(a[fm][3])
                             : "r"(addr));
            }
            unsigned bf[4][4];
#pragma unroll
            for (int fp = 0; fp < 4; fp++) {
                int n0 = wn * 64 + fp * 16;
                int row = n0 + (lane & 7) + ((lane >> 4) & 1) * 8;
                int kcol = kb + ((lane >> 3) & 1) * 8;
                unsigned addr = (unsigned)__cvta_generic_to_shared(Bs[buf] + row * 40 + kcol);
                asm volatile("ldmatrix.sync.aligned.m8n8.x4.shared.b16 {%0,%1,%2,%3}, [%4];\n"
                             : "=r"(bf[fp][0]), "=r"(bf[fp][1]), "=r"(bf[fp][2]), "=r"(bf[fp][3])
                             : "r"(addr));
            }
#pragma unroll
            for (int fm = 0; fm < 2; fm++)
#pragma unroll
                for (int fp = 0; fp < 4; fp++)
#pragma unroll
                    for (int hh = 0; hh < 2; hh++) {
                        float* c = accv[fm][fp * 2 + hh];
                        asm volatile(
                            "mma.sync.aligned.m16n8k16.row.col.f32.f16.f16.f32 "
                            "{%0,%1,%2,%3}, {%4,%5,%6,%7}, {%8,%9}, {%0,%1,%2,%3};\n"
                            : "+f"(c[0]), "+f"(c[1]), "+f"(c[2]), "+f"(c[3])
                            : "r"(a[fm][0]), "r"(a[fm][1]), "r"(a[fm][2]), "r"(a[fm][3]),
                              "r"(bf[fp][hh * 2]), "r"(bf[fp][hh * 2 + 1]));
                    }
        }
    };

    // prologue
    loadA(0);
    loadB(0, 0);
    asm volatile("cp.async.commit_group;\n");
    stsA(0);
    asm volatile("cp.async.wait_group 0;\n");
    __syncthreads();

    const int NKT = KTOT / 32;   // 33
    for (int kt = 0; kt < NKT; ++kt) {
        int cur = kt & 1;
        if (kt < NKT - 1) {
            loadA(kt + 1);
            loadB(kt + 1, 1 - cur);
            asm volatile("cp.async.commit_group;\n");
        }
        compute(cur);
        if (kt < NKT - 1) {
            stsA(1 - cur);
            asm volatile("cp.async.wait_group 0;\n");
            __syncthreads();
        }
    }

    // epilogue: stage through shared so [o][p] stores are coalesced
    __syncthreads();
#pragma unroll
    for (int ci = 0; ci < 4; ci++) {
        if (wn == (ci >> 1)) {
            const int fbase = (ci & 1) * 4;
#pragma unroll
            for (int fm = 0; fm < 2; fm++)
#pragma unroll
                for (int f = 0; f < 4; f++) {
                    int fn = fbase + f;
#pragma unroll
                    for (int e = 0; e < 4; e++) {
                        int row = wm * 32 + fm * 16 + (lane >> 2) + (e >> 1) * 8;
                        int col = f * 8 + 2 * (lane & 3) + (e & 1);
                        Ep[row * 33 + col] = accv[fm][fn][e];
                    }
                }
        }
        __syncthreads();
        for (int idx = tid; idx < 32 * 128; idx += 256) {
            int ol = idx >> 7, m = idx & 127;
            int o = o0 + ci * 32 + ol;
            float v = Ep[m * 33 + ol] + bias[o];
            v = fmaxf(v, 0.0f);
            out[(((size_t)(b * OC_ + o)) << 12) + p0 + m] = v;
        }
        __syncthreads();
    }
}

// ============================================================
extern "C" void kernel_launch(void* const* d_in, const int* in_sizes, int n_in,
                              void* d_out, int out_size) {
    const float* feat = (const float*)d_in[0];
    const float* w    = (const float*)d_in[1];
    const float* bias = (const float*)d_in[2];
    float* out = (float*)d_out;

    convW_kernel<<<(OC_ * KTOT + 255) / 256, 256>>>(w);
    corr_kernel<<<dim3(2, 8, 16), 256>>>(feat);
    inv_kernel<<<(B_ * HW_) / 256, 256>>>();
    combine_kernel<<<(B_ * 32 * HW_) / 256, 256>>>();
    gemm_kernel<<<dim3(8, 32, 8), 256>>>(feat, bias, out);
}

// round 2
// speedup vs baseline: 1.1343x; 1.1343x over previous
#include <cuda_runtime.h>
#include <cuda_fp16.h>
#include <cstdint>
#include <math.h>

// feature: [8,1024,64,64] f32 ; conv_w: [1024,1049] ; conv_b: [1024] ; out f32 same shape
// cat channels: 0..1023 feature, 1024..1048 corr (j = cc*5+r), padded to 1056.

#define B_      8
#define C_      1024
#define HW_     4096
#define OC_     1024
#define KTOT    1056
#define KREAL   1049
#define NG      4         // channel groups in corr kernel

// ---------------- scratch ----------------
__device__ __half g_Wh[OC_ * KTOT];                    // fp16 weights, zero-padded
__device__ __half g_Ah[(size_t)B_ * KTOT * HW_];       // fp16 A matrix [b][1056][4096]
__device__ float  g_sspart[NG * B_ * HW_];
__device__ float  g_inv[B_ * HW_];
__device__ float  g_accpart[NG * B_ * 25 * HW_];

// ============================================================
// K0: conv_w -> fp16, pad K to 1056
// ============================================================
__global__ void convW_kernel(const float* __restrict__ w) {
    int idx = blockIdx.x * 256 + threadIdx.x;
    if (idx >= OC_ * KTOT) return;
    int o = idx / KTOT, k = idx - o * KTOT;
    float v = (k < KREAL) ? w[o * KREAL + k] : 0.0f;
    g_Wh[idx] = __float2half(v);
}

// ============================================================
// K1: corr partials + sumsq + fp16 feature write (free side-effect).
// 32x32 pixel tile, 4 y-pixels per thread (register blocking).
// 4 channel groups of 256; 4 channels/iter double-buffered cp.async.
// ============================================================
__global__ __launch_bounds__(256) void corr_kernel(const float* __restrict__ feat) {
    __shared__ float tile[2][4][36 * 40];     // 2 bufs x 4ch x 36rows x 40cols = 46080 B

    const int tid = threadIdx.x;
    const int tx = tid & 31, ty = tid >> 5;
    const int x0 = blockIdx.x * 32, y0 = blockIdx.y * 32;
    const int b = blockIdx.z >> 2, g = blockIdx.z & 3;
    const float* fb = feat + (size_t)b * C_ * HW_;
    __half* ah = g_Ah + ((size_t)b * KTOT << 12);
    const int cbase = g * 256;

    float acc[25][4];
    float ss[4];
#pragma unroll
    for (int j = 0; j < 25; j++)
#pragma unroll
        for (int yy = 0; yy < 4; yy++) acc[j][yy] = 0.0f;
#pragma unroll
    for (int yy = 0; yy < 4; yy++) ss[yy] = 0.0f;

    auto load4 = [&](int c0, int buf) {
        // 1440 16B chunks: 4ch x 36 rows x 10 chunks
#pragma unroll 2
        for (int u = tid; u < 1440; u += 256) {
            int cc = u / 360, pos = u - cc * 360;
            int j = pos / 10, i = pos - j * 10;
            int gy = y0 - 2 + j;
            int gx0 = x0 - 4 + i * 4;
            bool valid = ((unsigned)gy < 64u) && ((unsigned)gx0 < 64u);
            const float* src = fb + (size_t)(c0 + cc) * HW_ + (valid ? (gy * 64 + gx0) : 0);
            unsigned dst = (unsigned)__cvta_generic_to_shared(&tile[buf][cc][j * 40 + i * 4]);
            int sz = valid ? 16 : 0;
            asm volatile("cp.async.ca.shared.global [%0], [%1], 16, %2;\n"
                         :: "r"(dst), "l"(src), "r"(sz));
        }
    };

    load4(cbase, 0);
    asm volatile("cp.async.commit_group;\n");

    for (int it = 0; it < 64; ++it) {
        if (it < 63) {
            load4(cbase + (it + 1) * 4, (it + 1) & 1);
            asm volatile("cp.async.commit_group;\n");
            asm volatile("cp.async.wait_group 1;\n");
        } else {
            asm volatile("cp.async.wait_group 0;\n");
        }
        __syncthreads();
        const int cb = it & 1;
#pragma unroll
        for (int q = 0; q < 4; q++) {
            const float* tq = &tile[cb][q][0];
            const int c = cbase + it * 4 + q;
            float cen[4];
#pragma unroll
            for (int yy = 0; yy < 4; yy++) {
                cen[yy] = tq[(ty * 4 + yy + 2) * 40 + tx + 4];
                ss[yy] += cen[yy] * cen[yy];
                ah[((size_t)c << 12) + (y0 + ty * 4 + yy) * 64 + x0 + tx] = __float2half(cen[yy]);
            }
#pragma unroll
            for (int cc = 0; cc < 5; cc++) {
#pragma unroll
                for (int ro = 0; ro < 8; ro++) {
                    float t = tq[(ty * 4 + ro) * 40 + tx + cc + 2];
#pragma unroll
                    for (int yy = 0; yy < 4; yy++) {
                        int r = ro - yy;
                        if (r >= 0 && r < 5) acc[cc * 5 + r][yy] += t * cen[yy];
                    }
                }
            }
        }
        __syncthreads();
    }

#pragma unroll
    for (int yy = 0; yy < 4; yy++) {
        int p = (y0 + ty * 4 + yy) * 64 + x0 + tx;
        g_sspart[(g * B_ + b) * HW_ + p] = ss[yy];
#pragma unroll
        for (int j = 0; j < 25; j++)
            g_accpart[((g * B_ + b) * 25 + j) * HW_ + p] = acc[j][yy];
    }
}

// ============================================================
// K2: inv = 1/max(||f||, eps)
// ============================================================
__global__ void inv_kernel() {
    int idx = blockIdx.x * 256 + threadIdx.x;
    if (idx >= B_ * HW_) return;
    float ssv = 0.0f;
#pragma unroll
    for (int g = 0; g < NG; g++) ssv += g_sspart[g * B_ * HW_ + idx];
    g_inv[idx] = 1.0f / fmaxf(sqrtf(ssv), 1e-12f);
}

// ============================================================
// K3: normalized corr -> fp16 A channels 1024..1055 (pad planes zero)
// ============================================================
__global__ void combine_kernel() {
    int idx = blockIdx.x * 256 + threadIdx.x;     // B_*32*HW_
    if (idx >= B_ * 32 * HW_) return;
    int p = idx & (HW_ - 1);
    int j = (idx >> 12) & 31;
    int b = idx >> 17;
    float v = 0.0f;
    if (j < 25) {
        int y = p >> 6, x = p & 63;
        int ccs = j / 5, r = j - ccs * 5;
        int tyy = y + r - 2, txx = x + ccs - 2;
        if ((unsigned)tyy < 64u && (unsigned)txx < 64u) {
            float a = 0.0f;
#pragma unroll
            for (int g = 0; g < NG; g++)
                a += g_accpart[((g * B_ + b) * 25 + j) * HW_ + p];
            v = a * g_inv[b * HW_ + p] * g_inv[b * HW_ + tyy * 64 + txx];
        }
    }
    g_Ah[((size_t)(b * KTOT + C_ + j) << 12) + p] = __float2half(v);
}

// ============================================================
// K4: GEMM  out[b,o,p] = relu( sum_k Wh[o,k]*Ah[b,k,p] + bias[o] )
// CTA tile 128p x 256o x 32k, 256 threads (8 warps: 4 along m, 2 along n),
// 3-stage cp.async pipeline, both operands fp16 from global.
// ============================================================
#define NKT 33
#define A_STAGE 8704        // 32*136*2
#define B_STAGE 20480       // 256*40*2

__global__ __launch_bounds__(256) void gemm_kernel(const float* __restrict__ bias,
                                                   float* __restrict__ out) {
    extern __shared__ __align__(16) unsigned char SM[];
    __half* As[3] = { (__half*)SM, (__half*)(SM + A_STAGE), (__half*)(SM + 2 * A_STAGE) };
    __half* Bs[3] = { (__half*)(SM + 3 * A_STAGE),
                      (__half*)(SM + 3 * A_STAGE + B_STAGE),
                      (__half*)(SM + 3 * A_STAGE + 2 * B_STAGE) };
    float* Ep = (float*)SM;   // [128][33] epilogue staging

    const int tid = threadIdx.x;
    const int lane = tid & 31, wid = tid >> 5;
    const int wm = wid & 3, wn = wid >> 2;
    const int o0 = blockIdx.x * 256;
    const int p0 = blockIdx.y * 128;
    const int b  = blockIdx.z;

    const __half* aBase = g_Ah + ((size_t)b * KTOT << 12) + p0;

    float accv[2][16][4];
#pragma unroll
    for (int i = 0; i < 2; i++)
#pragma unroll
        for (int j = 0; j < 16; j++)
#pragma unroll
            for (int e = 0; e < 4; e++) accv[i][j][e] = 0.0f;

    auto loadStage = [&](int kt, int buf) {
        // A: [k 32][m 128] fp16 -> 512 16B chunks
#pragma unroll
        for (int s = 0; s < 2; s++) {
            int u = tid + s * 256;
            int row = u >> 4, ch = u & 15;
            const __half* src = aBase + (((size_t)(kt * 32 + row)) << 12) + ch * 8;
            unsigned dst = (unsigned)__cvta_generic_to_shared(As[buf] + row * 136 + ch * 8);
            asm volatile("cp.async.ca.shared.global [%0], [%1], 16;\n" :: "r"(dst), "l"(src));
        }
        // B: [n 256][k 32] fp16 -> 1024 16B chunks
#pragma unroll
        for (int s = 0; s < 4; s++) {
            int u = tid + s * 256;
            int orow = u >> 2, q = u & 3;
            const __half* src = g_Wh + (size_t)(o0 + orow) * KTOT + kt * 32 + q * 8;
            unsigned dst = (unsigned)__cvta_generic_to_shared(Bs[buf] + orow * 40 + q * 8);
            asm volatile("cp.async.ca.shared.global [%0], [%1], 16;\n" :: "r"(dst), "l"(src));
        }
        asm volatile("cp.async.commit_group;\n");
    };

    auto compute = [&](int buf) {
#pragma unroll
        for (int ks = 0; ks < 2; ks++) {
            const int kb = ks * 16;
            unsigned a[2][4];
#pragma unroll
            for (int fm = 0; fm < 2; fm++) {
                int kk = kb + ((lane >> 4) & 1) * 8 + (lane & 7);
                int mm = wm * 32 + fm * 16 + ((lane >> 3) & 1) * 8;
                unsigned addr = (unsigned)__cvta_generic_to_shared(As[buf] + kk * 136 + mm);
                asm volatile("ldmatrix.sync.aligned.m8n8.x4.trans.shared.b16 {%0,%1,%2,%3}, [%4];\n"
                             : "=r"(a[fm][0]), "=r"(a[fm][1]), "=r"(a[fm][2]), "=r"(a[fm][3])
                             : "r"(addr));
            }
            unsigned bf[8][4];
#pragma unroll
            for (int fp = 0; fp < 8; fp++) {
                int row = wn * 128 + fp * 16 + (lane & 7) + ((lane >> 4) & 1) * 8;
                int kcol = kb + ((lane >> 3) & 1) * 8;
                unsigned addr = (unsigned)__cvta_generic_to_shared(Bs[buf] + row * 40 + kcol);
                asm volatile("ldmatrix.sync.aligned.m8n8.x4.shared.b16 {%0,%1,%2,%3}, [%4];\n"
                             : "=r"(bf[fp][0]), "=r"(bf[fp][1]), "=r"(bf[fp][2]), "=r"(bf[fp][3])
                             : "r"(addr));
            }
#pragma unroll
            for (int fm = 0; fm < 2; fm++)
#pragma unroll
                for (int fp = 0; fp < 8; fp++)
#pragma unroll
                    for (int hh = 0; hh < 2; hh++) {
                        float* c = accv[fm][fp * 2 + hh];
                        asm volatile(
                            "mma.sync.aligned.m16n8k16.row.col.f32.f16.f16.f32 "
                            "{%0,%1,%2,%3}, {%4,%5,%6,%7}, {%8,%9}, {%0,%1,%2,%3};\n"
                            : "+f"(c[0]), "+f"(c[1]), "+f"(c[2]), "+f"(c[3])
                            : "r"(a[fm][0]), "r"(a[fm][1]), "r"(a[fm][2]), "r"(a[fm][3]),
                              "r"(bf[fp][hh * 2]), "r"(bf[fp][hh * 2 + 1]));
                    }
        }
    };

    // prologue: stages 0,1
    loadStage(0, 0);
    loadStage(1, 1);

    for (int kt = 0; kt < NKT; ++kt) {
        asm volatile("cp.async.wait_group 1;\n");
        __syncthreads();
        if (kt + 2 < NKT) loadStage(kt + 2, (kt + 2) % 3);
        else asm volatile("cp.async.commit_group;\n");   // empty group keeps FIFO math uniform
        compute(kt % 3);
    }

    // epilogue: stage through shared for coalesced [o][p] stores
    __syncthreads();
#pragma unroll
    for (int ci = 0; ci < 8; ci++) {
        if (wn == (ci >> 2)) {
            const int fbase = (ci & 3) * 4;
#pragma unroll
            for (int fm = 0; fm < 2; fm++)
#pragma unroll
                for (int f = 0; f < 4; f++) {
                    int fn = fbase + f;
#pragma unroll
                    for (int e = 0; e < 4; e++) {
                        int row = wm * 32 + fm * 16 + (lane >> 2) + (e >> 1) * 8;
                        int col = f * 8 + 2 * (lane & 3) + (e & 1);
                        Ep[row * 33 + col] = accv[fm][fn][e];
                    }
                }
        }
        __syncthreads();
        for (int idx = tid; idx < 32 * 128; idx += 256) {
            int ol = idx >> 7, m = idx & 127;
            int o = o0 + ci * 32 + ol;
            float v = Ep[m * 33 + ol] + bias[o];
            out[(((size_t)(b * OC_ + o)) << 12) + p0 + m] = fmaxf(v, 0.0f);
        }
        __syncthreads();
    }
}

// ============================================================
extern "C" void kernel_launch(void* const* d_in, const int* in_sizes, int n_in,
                              void* d_out, int out_size) {
    const float* feat = (const float*)d_in[0];
    const float* w    = (const float*)d_in[1];
    const float* bias = (const float*)d_in[2];
    float* out = (float*)d_out;

    static bool attr_set = false;
    if (!attr_set) {
        cudaFuncSetAttribute(gemm_kernel, cudaFuncAttributeMaxDynamicSharedMemorySize,
                             3 * (A_STAGE + B_STAGE));
        attr_set = true;
    }

    convW_kernel<<<(OC_ * KTOT + 255) / 256, 256>>>(w);
    corr_kernel<<<dim3(2, 2, B_ * NG), 256>>>(feat);
    inv_kernel<<<(B_ * HW_) / 256, 256>>>();
    combine_kernel<<<(B_ * 32 * HW_) / 256, 256>>>();
    gemm_kernel<<<dim3(4, 32, B_), 256, 3 * (A_STAGE + B_STAGE)>>>(bias, out);
}

// round 5
// speedup vs baseline: 1.3010x; 1.1470x over previous
#include <cuda_runtime.h>
#include <cuda_fp16.h>
#include <cstdint>
#include <math.h>

// feature: [8,1024,64,64] f32 ; conv_w: [1024,1049] ; conv_b: [1024] ; out f32 same shape
// cat channels: 0..1023 feature, 1024..1048 corr (j = cc*5+r), padded to 1056.

#define B_      8
#define C_      1024
#define HW_     4096
#define OC_     1024
#define KTOT    1056
#define KREAL   1049
#define NG      4

// ---------------- scratch ----------------
__device__ __half g_Wh[OC_ * KTOT];                    // fp16 weights, zero-padded
__device__ __half g_Ah[(size_t)B_ * KTOT * HW_];       // fp16 A matrix [b][1056][4096]
__device__ float  g_sspart[NG * B_ * HW_];
__device__ float  g_inv[B_ * HW_];
__device__ float  g_accpart[NG * B_ * 25 * HW_];

// ============================================================
// K0: conv_w -> fp16, pad K to 1056
// ============================================================
__global__ void convW_kernel(const float* __restrict__ w) {
    int idx = blockIdx.x * 256 + threadIdx.x;
    if (idx >= OC_ * KTOT) return;
    int o = idx / KTOT, k = idx - o * KTOT;
    float v = (k < KREAL) ? w[o * KREAL + k] : 0.0f;
    g_Wh[idx] = __float2half(v);
}

// ============================================================
// K1: corr partials + sumsq + fp16 feature write (free side-effect).
// ============================================================
__global__ __launch_bounds__(256) void corr_kernel(const float* __restrict__ feat) {
    __shared__ float tile[2][4][36 * 40];

    const int tid = threadIdx.x;
    const int tx = tid & 31, ty = tid >> 5;
    const int x0 = blockIdx.x * 32, y0 = blockIdx.y * 32;
    const int b = blockIdx.z >> 2, g = blockIdx.z & 3;
    const float* fb = feat + (size_t)b * C_ * HW_;
    __half* ah = g_Ah + ((size_t)b * KTOT << 12);
    const int cbase = g * 256;

    float acc[25][4];
    float ss[4];
#pragma unroll
    for (int j = 0; j < 25; j++)
#pragma unroll
        for (int yy = 0; yy < 4; yy++) acc[j][yy] = 0.0f;
#pragma unroll
    for (int yy = 0; yy < 4; yy++) ss[yy] = 0.0f;

    auto load4 = [&](int c0, int buf) {
#pragma unroll 2
        for (int u = tid; u < 1440; u += 256) {
            int cc = u / 360, pos = u - cc * 360;
            int j = pos / 10, i = pos - j * 10;
            int gy = y0 - 2 + j;
            int gx0 = x0 - 4 + i * 4;
            bool valid = ((unsigned)gy < 64u) && ((unsigned)gx0 < 64u);
            const float* src = fb + (size_t)(c0 + cc) * HW_ + (valid ? (gy * 64 + gx0) : 0);
            unsigned dst = (unsigned)__cvta_generic_to_shared(&tile[buf][cc][j * 40 + i * 4]);
            int sz = valid ? 16 : 0;
            asm volatile("cp.async.ca.shared.global [%0], [%1], 16, %2;\n"
                         :: "r"(dst), "l"(src), "r"(sz));
        }
    };

    load4(cbase, 0);
    asm volatile("cp.async.commit_group;\n");

    for (int it = 0; it < 64; ++it) {
        if (it < 63) {
            load4(cbase + (it + 1) * 4, (it + 1) & 1);
            asm volatile("cp.async.commit_group;\n");
            asm volatile("cp.async.wait_group 1;\n");
        } else {
            asm volatile("cp.async.wait_group 0;\n");
        }
        __syncthreads();
        const int cb = it & 1;
#pragma unroll
        for (int q = 0; q < 4; q++) {
            const float* tq = &tile[cb][q][0];
            const int c = cbase + it * 4 + q;
            float cen[4];
#pragma unroll
            for (int yy = 0; yy < 4; yy++) {
                cen[yy] = tq[(ty * 4 + yy + 2) * 40 + tx + 4];
                ss[yy] += cen[yy] * cen[yy];
                ah[((size_t)c << 12) + (y0 + ty * 4 + yy) * 64 + x0 + tx] = __float2half(cen[yy]);
            }
#pragma unroll
            for (int cc = 0; cc < 5; cc++) {
#pragma unroll
                for (int ro = 0; ro < 8; ro++) {
                    float t = tq[(ty * 4 + ro) * 40 + tx + cc + 2];
#pragma unroll
                    for (int yy = 0; yy < 4; yy++) {
                        int r = ro - yy;
                        if (r >= 0 && r < 5) acc[cc * 5 + r][yy] += t * cen[yy];
                    }
                }
            }
        }
        __syncthreads();
    }

#pragma unroll
    for (int yy = 0; yy < 4; yy++) {
        int p = (y0 + ty * 4 + yy) * 64 + x0 + tx;
        g_sspart[(g * B_ + b) * HW_ + p] = ss[yy];
#pragma unroll
        for (int j = 0; j < 25; j++)
            g_accpart[((g * B_ + b) * 25 + j) * HW_ + p] = acc[j][yy];
    }
}

// ============================================================
// K2: inv = 1/max(||f||, eps)
// ============================================================
__global__ void inv_kernel() {
    int idx = blockIdx.x * 256 + threadIdx.x;
    if (idx >= B_ * HW_) return;
    float ssv = 0.0f;
#pragma unroll
    for (int g = 0; g < NG; g++) ssv += g_sspart[g * B_ * HW_ + idx];
    g_inv[idx] = 1.0f / fmaxf(sqrtf(ssv), 1e-12f);
}

// ============================================================
// K3: normalized corr -> fp16 A channels 1024..1055
// ============================================================
__global__ void combine_kernel() {
    int idx = blockIdx.x * 256 + threadIdx.x;     // B_*32*HW_
    if (idx >= B_ * 32 * HW_) return;
    int p = idx & (HW_ - 1);
    int j = (idx >> 12) & 31;
    int b = idx >> 17;
    float v = 0.0f;
    if (j < 25) {
        int y = p >> 6, x = p & 63;
        int ccs = j / 5, r = j - ccs * 5;
        int tyy = y + r - 2, txx = x + ccs - 2;
        if ((unsigned)tyy < 64u && (unsigned)txx < 64u) {
            float a = 0.0f;
#pragma unroll
            for (int g = 0; g < NG; g++)
                a += g_accpart[((g * B_ + b) * 25 + j) * HW_ + p];
            v = a * g_inv[b * HW_ + p] * g_inv[b * HW_ + tyy * 64 + txx];
        }
    }
    g_Ah[((size_t)(b * KTOT + C_ + j) << 12) + p] = __float2half(v);
}

// ============================================================
// K4: GEMM  out[b,o,p] = relu( sum_k Wh[o,k]*Ah[b,k,p] + bias[o] )
// CTA tile 128p x 128o x 32k, 256 threads (8 warps: 4 m, 2 n),
// 4-stage cp.async pipeline, 2 CTAs/SM.
// ============================================================
#define NKT 33
#define A_STAGE 8704        // 32*136*2
#define B_STAGE 10240       // 128*40*2
#define NSTG 4
#define GEMM_SMEM (NSTG * (A_STAGE + B_STAGE))

__global__ __launch_bounds__(256, 2) void gemm_kernel(const float* __restrict__ bias,
                                                      float* __restrict__ out) {
    extern __shared__ __align__(16) unsigned char SM[];
    __half* As[NSTG];
    __half* Bs[NSTG];
#pragma unroll
    for (int s = 0; s < NSTG; s++) {
        As[s] = (__half*)(SM + s * (A_STAGE + B_STAGE));
        Bs[s] = (__half*)(SM + s * (A_STAGE + B_STAGE) + A_STAGE);
    }
    float* Ep = (float*)SM;   // [128][33] epilogue staging

    const int tid = threadIdx.x;
    const int lane = tid & 31, wid = tid >> 5;
    const int wm = wid & 3, wn = wid >> 2;
    const int o0 = blockIdx.x * 128;
    const int p0 = blockIdx.y * 128;
    const int b  = blockIdx.z;

    const __half* aBase = g_Ah + ((size_t)b * KTOT << 12) + p0;

    float accv[2][8][4];
#pragma unroll
    for (int i = 0; i < 2; i++)
#pragma unroll
        for (int j = 0; j < 8; j++)
#pragma unroll
            for (int e = 0; e < 4; e++) accv[i][j][e] = 0.0f;

    auto loadStage = [&](int kt, int buf) {
        // A: [k 32][m 128] fp16 -> 512 16B chunks
#pragma unroll
        for (int s = 0; s < 2; s++) {
            int u = tid + s * 256;
            int row = u >> 4, ch = u & 15;
            const __half* src = aBase + (((size_t)(kt * 32 + row)) << 12) + ch * 8;
            unsigned dst = (unsigned)__cvta_generic_to_shared(As[buf] + row * 136 + ch * 8);
            asm volatile("cp.async.ca.shared.global [%0], [%1], 16;\n" :: "r"(dst), "l"(src));
        }
        // B: [n 128][k 32] fp16 -> 512 16B chunks
#pragma unroll
        for (int s = 0; s < 2; s++) {
            int u = tid + s * 256;
            int orow = u >> 2, q = u & 3;
            const __half* src = g_Wh + (size_t)(o0 + orow) * KTOT + kt * 32 + q * 8;
            unsigned dst = (unsigned)__cvta_generic_to_shared(Bs[buf] + orow * 40 + q * 8);
            asm volatile("cp.async.ca.shared.global [%0], [%1], 16;\n" :: "r"(dst), "l"(src));
        }
        asm volatile("cp.async.commit_group;\n");
    };

    auto compute = [&](int buf) {
#pragma unroll
        for (int ks = 0; ks < 2; ks++) {
            const int kb = ks * 16;
            unsigned a[2][4];
#pragma unroll
            for (int fm = 0; fm < 2; fm++) {
                int kk = kb + ((lane >> 4) & 1) * 8 + (lane & 7);
                int mm = wm * 32 + fm * 16 + ((lane >> 3) & 1) * 8;
                unsigned addr = (unsigned)__cvta_generic_to_shared(As[buf] + kk * 136 + mm);
                asm volatile("ldmatrix.sync.aligned.m8n8.x4.trans.shared.b16 {%0,%1,%2,%3}, [%4];\n"
                             : "=r"(a[fm][0]), "=r"(a[fm][1]), "=r"(a[fm][2]), "=r"(a[fm][3])
                             : "r"(addr));
            }
            unsigned bf[4][4];
#pragma unroll
            for (int fp = 0; fp < 4; fp++) {
                int row = wn * 64 + fp * 16 + (lane & 7) + ((lane >> 4) & 1) * 8;
                int kcol = kb + ((lane >> 3) & 1) * 8;
                unsigned addr = (unsigned)__cvta_generic_to_shared(Bs[buf] + row * 40 + kcol);
                asm volatile("ldmatrix.sync.aligned.m8n8.x4.shared.b16 {%0,%1,%2,%3}, [%4];\n"
                             : "=r"(bf[fp][0]), "=r"(bf[fp][1]), "=r"(bf[fp][2]), "=r"(bf[fp][3])
                             : "r"(addr));
            }
#pragma unroll
            for (int fm = 0; fm < 2; fm++)
#pragma unroll
                for (int fp = 0; fp < 4; fp++)
#pragma unroll
                    for (int hh = 0; hh < 2; hh++) {
                        float* c = accv[fm][fp * 2 + hh];
                        asm volatile(
                            "mma.sync.aligned.m16n8k16.row.col.f32.f16.f16.f32 "
                            "{%0,%1,%2,%3}, {%4,%5,%6,%7}, {%8,%9}, {%0,%1,%2,%3};\n"
                            : "+f"(c[0]), "+f"(c[1]), "+f"(c[2]), "+f"(c[3])
                            : "r"(a[fm][0]), "r"(a[fm][1]), "r"(a[fm][2]), "r"(a[fm][3]),
                              "r"(bf[fp][hh * 2]), "r"(bf[fp][hh * 2 + 1]));
                    }
        }
    };

    // prologue: stages 0,1,2
    loadStage(0, 0);
    loadStage(1, 1);
    loadStage(2, 2);

    for (int kt = 0; kt < NKT; ++kt) {
        asm volatile("cp.async.wait_group 2;\n");
        __syncthreads();
        if (kt + 3 < NKT) loadStage(kt + 3, (kt + 3) % NSTG);
        else asm volatile("cp.async.commit_group;\n");   // keep FIFO accounting uniform
        compute(kt % NSTG);
    }

    // epilogue: stage through shared for coalesced [o][p] stores
    __syncthreads();
#pragma unroll
    for (int ci = 0; ci < 4; ci++) {
        if (wn == (ci >> 1)) {
            const int fbase = (ci & 1) * 4;
#pragma unroll
            for (int fm = 0; fm < 2; fm++)
#pragma unroll
                for (int f = 0; f < 4; f++) {
                    int fn = fbase + f;
#pragma unroll
                    for (int e = 0; e < 4; e++) {
                        int row = wm * 32 + fm * 16 + (lane >> 2) + (e >> 1) * 8;
                        int col = f * 8 + 2 * (lane & 3) + (e & 1);
                        Ep[row * 33 + col] = accv[fm][fn][e];
                    }
                }
        }
        __syncthreads();
        for (int idx = tid; idx < 32 * 128; idx += 256) {
            int ol = idx >> 7, m = idx & 127;
            int o = o0 + ci * 32 + ol;
            float v = Ep[m * 33 + ol] + bias[o];
            out[(((size_t)(b * OC_ + o)) << 12) + p0 + m] = fmaxf(v, 0.0f);
        }
        __syncthreads();
    }
}

// ============================================================
extern "C" void kernel_launch(void* const* d_in, const int* in_sizes, int n_in,
                              void* d_out, int out_size) {
    const float* feat = (const float*)d_in[0];
    const float* w    = (const float*)d_in[1];
    const float* bias = (const float*)d_in[2];
    float* out = (float*)d_out;

    static bool attr_set = false;
    if (!attr_set) {
        cudaFuncSetAttribute(gemm_kernel, cudaFuncAttributeMaxDynamicSharedMemorySize,
                             GEMM_SMEM);
        attr_set = true;
    }

    convW_kernel<<<(OC_ * KTOT + 255) / 256, 256>>>(w);
    corr_kernel<<<dim3(2, 2, B_ * NG), 256>>>(feat);
    inv_kernel<<<(B_ * HW_) / 256, 256>>>();
    combine_kernel<<<(B_ * 32 * HW_) / 256, 256>>>();
    gemm_kernel<<<dim3(8, 32, B_), 256, GEMM_SMEM>>>(bias, out);
}

// round 7
// speedup vs baseline: 1.5342x; 1.1792x over previous
#include <cuda_runtime.h>
#include <cuda_fp16.h>
#include <cstdint>
#include <math.h>

// feature: [8,1024,64,64] f32 ; conv_w: [1024,1049] ; conv_b: [1024] ; out f32 same shape
// cat channels: 0..1023 feature, 1024..1048 corr (j = cc*5+r), padded to 1056.

#define B_      8
#define C_      1024
#define HW_     4096
#define OC_     1024
#define KTOT    1056
#define KREAL   1049
#define NG      8

// ---------------- scratch ----------------
__device__ __half g_Wh[OC_ * KTOT];                          // fp16 weights, zero-padded
__device__ __half g_Ah[(size_t)B_ * KTOT * HW_];             // fp16 A matrix [b][1056][4096]
__device__ __align__(16) float g_sspart[NG * B_ * HW_];
__device__ __align__(16) float g_inv[B_ * HW_];
__device__ __align__(16) float g_accpart[(size_t)NG * B_ * 25 * HW_];

// ---------------- f32x2 helpers ----------------
typedef unsigned long long u64t;
__device__ __forceinline__ u64t pk2(float a, float b) {
    u64t r; asm("mov.b64 %0, {%1, %2};" : "=l"(r) : "f"(a), "f"(b)); return r;
}
__device__ __forceinline__ void fma2(u64t& d, u64t a, u64t b) {
    asm("fma.rn.f32x2 %0, %1, %2, %0;" : "+l"(d) : "l"(a), "l"(b));
}
__device__ __forceinline__ float2 up2(u64t a) {
    float2 r; asm("mov.b64 {%0, %1}, %2;" : "=f"(r.x), "=f"(r.y) : "l"(a)); return r;
}

// ============================================================
// K2(fused): convW (conv_w -> fp16 padded) + inv (1/max(||f||,eps))
// ============================================================
__global__ void fuse_kernel(const float* __restrict__ w) {
    int idx = blockIdx.x * 256 + threadIdx.x;
    if (idx < OC_ * KTOT) {
        int o = idx / KTOT, k = idx - o * KTOT;
        float v = (k < KREAL) ? w[o * KREAL + k] : 0.0f;
        g_Wh[idx] = __float2half(v);
    }
    if (idx < B_ * HW_) {
        float ssv = 0.0f;
#pragma unroll
        for (int g = 0; g < NG; g++) ssv += g_sspart[g * B_ * HW_ + idx];
        g_inv[idx] = 1.0f / fmaxf(sqrtf(ssv), 1e-12f);
    }
}

// ============================================================
// K1: corr partials + sumsq + fp16 feature write.
// 32x32 tile, 2x2 px/thread, f32x2 FMA, NG=8 channel groups (128 ch each).
// ============================================================
__global__ __launch_bounds__(256, 2) void corr_kernel(const float* __restrict__ feat) {
    __shared__ float tile[2][4][36 * 40];

    const int tid = threadIdx.x;
    const int tx = tid & 15, ty = tid >> 4;         // 16x16 threads, 2x2 px each
    const int x0 = blockIdx.x * 32, y0 = blockIdx.y * 32;
    const int b = blockIdx.z >> 3, g = blockIdx.z & 7;
    const float* fb = feat + (size_t)b * C_ * HW_;
    __half* ah = g_Ah + ((size_t)b * KTOT << 12);
    const int cbase = g * 128;

    u64t acc2[25][2];                                // [j][yy], lanes = xx pair
    u64t ss2[2];
#pragma unroll
    for (int j = 0; j < 25; j++) { acc2[j][0] = 0ull; acc2[j][1] = 0ull; }
    ss2[0] = 0ull; ss2[1] = 0ull;

    auto load4 = [&](int c0, int buf) {
#pragma unroll 2
        for (int u = tid; u < 1440; u += 256) {
            int cc = u / 360, pos = u - cc * 360;
            int j = pos / 10, i = pos - j * 10;
            int gy = y0 - 2 + j;
            int gx0 = x0 - 4 + i * 4;
            bool valid = ((unsigned)gy < 64u) && ((unsigned)gx0 < 64u);
            const float* src = fb + (size_t)(c0 + cc) * HW_ + (valid ? (gy * 64 + gx0) : 0);
            unsigned dst = (unsigned)__cvta_generic_to_shared(&tile[buf][cc][j * 40 + i * 4]);
            int sz = valid ? 16 : 0;
            asm volatile("cp.async.ca.shared.global [%0], [%1], 16, %2;\n"
                         :: "r"(dst), "l"(src), "r"(sz));
        }
    };

    load4(cbase, 0);
    asm volatile("cp.async.commit_group;\n");

    for (int it = 0; it < 32; ++it) {
        if (it < 31) {
            load4(cbase + (it + 1) * 4, (it + 1) & 1);
            asm volatile("cp.async.commit_group;\n");
            asm volatile("cp.async.wait_group 1;\n");
        } else {
            asm volatile("cp.async.wait_group 0;\n");
        }
        __syncthreads();
        const int cb = it & 1;
#pragma unroll
        for (int q = 0; q < 4; q++) {
            const float* tq = &tile[cb][q][0];
            const int c = cbase + it * 4 + q;
            u64t cen2[2];
#pragma unroll
            for (int yy = 0; yy < 2; yy++) {
                float2 cf = *(const float2*)&tq[(2 * ty + yy + 2) * 40 + 2 * tx + 4];
                cen2[yy] = pk2(cf.x, cf.y);
                fma2(ss2[yy], cen2[yy], cen2[yy]);
                __half2 hv = __floats2half2_rn(cf.x, cf.y);
                *(__half2*)&ah[((size_t)c << 12) + (y0 + 2 * ty + yy) * 64 + x0 + 2 * tx] = hv;
            }
#pragma unroll
            for (int rr = 0; rr < 6; rr++) {
                const float* rp = &tq[(2 * ty + rr) * 40 + 2 * tx + 2];
                float2 p0 = *(const float2*)(rp);
                float2 p1 = *(const float2*)(rp + 2);
                float2 p2 = *(const float2*)(rp + 4);
                u64t t[5];
                t[0] = pk2(p0.x, p0.y);
                t[1] = pk2(p0.y, p1.x);
                t[2] = pk2(p1.x, p1.y);
                t[3] = pk2(p1.y, p2.x);
                t[4] = pk2(p2.x, p2.y);
#pragma unroll
                for (int cc = 0; cc < 5; cc++) {
                    if (rr <= 4) fma2(acc2[cc * 5 + rr][0], t[cc], cen2[0]);
                    if (rr >= 1) fma2(acc2[cc * 5 + rr - 1][1], t[cc], cen2[1]);
                }
            }
        }
        __syncthreads();
    }

#pragma unroll
    for (int yy = 0; yy < 2; yy++) {
        int p = (y0 + 2 * ty + yy) * 64 + x0 + 2 * tx;
        *(float2*)&g_sspart[(g * B_ + b) * HW_ + p] = up2(ss2[yy]);
#pragma unroll
        for (int j = 0; j < 25; j++)
            *(float2*)&g_accpart[((size_t)(g * B_ + b) * 25 + j) * HW_ + p] = up2(acc2[j][yy]);
    }
}

// ============================================================
// K3: normalized corr -> fp16 A channels 1024..1055
// ============================================================
__global__ void combine_kernel() {
    int idx = blockIdx.x * 256 + threadIdx.x;     // B_*32*HW_
    if (idx >= B_ * 32 * HW_) return;
    int p = idx & (HW_ - 1);
    int j = (idx >> 12) & 31;
    int b = idx >> 17;
    float v = 0.0f;
    if (j < 25) {
        int y = p >> 6, x = p & 63;
        int ccs = j / 5, r = j - ccs * 5;
        int tyy = y + r - 2, txx = x + ccs - 2;
        if ((unsigned)tyy < 64u && (unsigned)txx < 64u) {
            float a = 0.0f;
#pragma unroll
            for (int g = 0; g < NG; g++)
                a += g_accpart[((size_t)(g * B_ + b) * 25 + j) * HW_ + p];
            v = a * g_inv[b * HW_ + p] * g_inv[b * HW_ + tyy * 64 + txx];
        }
    }
    g_Ah[((size_t)(b * KTOT + C_ + j) << 12) + p] = __float2half(v);
}

// ============================================================
// K4: GEMM  out[b,o,p] = relu( sum_k Wh[o,k]*Ah[b,k,p] + bias[o] )
// CTA tile 128p x 128o x 32k, 256 threads, 4-stage cp.async, 2 CTAs/SM.
// ============================================================
#define NKT 33
#define A_STAGE 8704        // 32*136*2
#define B_STAGE 10240       // 128*40*2
#define NSTG 4
#define GEMM_SMEM (NSTG * (A_STAGE + B_STAGE))

__global__ __launch_bounds__(256, 2) void gemm_kernel(const float* __restrict__ bias,
                                                      float* __restrict__ out) {
    extern __shared__ __align__(16) unsigned char SM[];
    __half* As[NSTG];
    __half* Bs[NSTG];
#pragma unroll
    for (int s = 0; s < NSTG; s++) {
        As[s] = (__half*)(SM + s * (A_STAGE + B_STAGE));
        Bs[s] = (__half*)(SM + s * (A_STAGE + B_STAGE) + A_STAGE);
    }
    float* Ep = (float*)SM;   // [128][33] epilogue staging

    const int tid = threadIdx.x;
    const int lane = tid & 31, wid = tid >> 5;
    const int wm = wid & 3, wn = wid >> 2;
    const int o0 = blockIdx.x * 128;
    const int p0 = blockIdx.y * 128;
    const int b  = blockIdx.z;

    const __half* aBase = g_Ah + ((size_t)b * KTOT << 12) + p0;

    float accv[2][8][4];
#pragma unroll
    for (int i = 0; i < 2; i++)
#pragma unroll
        for (int j = 0; j < 8; j++)
#pragma unroll
            for (int e = 0; e < 4; e++) accv[i][j][e] = 0.0f;

    auto loadStage = [&](int kt, int buf) {
#pragma unroll
        for (int s = 0; s < 2; s++) {
            int u = tid + s * 256;
            int row = u >> 4, ch = u & 15;
            const __half* src = aBase + (((size_t)(kt * 32 + row)) << 12) + ch * 8;
            unsigned dst = (unsigned)__cvta_generic_to_shared(As[buf] + row * 136 + ch * 8);
            asm volatile("cp.async.cg.shared.global [%0], [%1], 16;\n" :: "r"(dst), "l"(src));
        }
#pragma unroll
        for (int s = 0; s < 2; s++) {
            int u = tid + s * 256;
            int orow = u >> 2, q = u & 3;
            const __half* src = g_Wh + (size_t)(o0 + orow) * KTOT + kt * 32 + q * 8;
            unsigned dst = (unsigned)__cvta_generic_to_shared(Bs[buf] + orow * 40 + q * 8);
            asm volatile("cp.async.cg.shared.global [%0], [%1], 16;\n" :: "r"(dst), "l"(src));
        }
        asm volatile("cp.async.commit_group;\n");
    };

    auto compute = [&](int buf) {
#pragma unroll
        for (int ks = 0; ks < 2; ks++) {
            const int kb = ks * 16;
            unsigned a[2][4];
#pragma unroll
            for (int fm = 0; fm < 2; fm++) {
                int kk = kb + ((lane >> 4) & 1) * 8 + (lane & 7);
                int mm = wm * 32 + fm * 16 + ((lane >> 3) & 1) * 8;
                unsigned addr = (unsigned)__cvta_generic_to_shared(As[buf] + kk * 136 + mm);
                asm volatile("ldmatrix.sync.aligned.m8n8.x4.trans.shared.b16 {%0,%1,%2,%3}, [%4];\n"
                             : "=r"(a[fm][0]), "=r"(a[fm][1]), "=r"(a[fm][2]), "=r"(a[fm][3])
                             : "r"(addr));
            }
            unsigned bf[4][4];
#pragma unroll
            for (int fp = 0; fp < 4; fp++) {
                int row = wn * 64 + fp * 16 + (lane & 7) + ((lane >> 4) & 1) * 8;
                int kcol = kb + ((lane >> 3) & 1) * 8;
                unsigned addr = (unsigned)__cvta_generic_to_shared(Bs[buf] + row * 40 + kcol);
                asm volatile("ldmatrix.sync.aligned.m8n8.x4.shared.b16 {%0,%1,%2,%3}, [%4];\n"
                             : "=r"(bf[fp][0]), "=r"(bf[fp][1]), "=r"(bf[fp][2]), "=r"(bf[fp][3])
                             : "r"(addr));
            }
#pragma unroll
            for (int fm = 0; fm < 2; fm++)
#pragma unroll
                for (int fp = 0; fp < 4; fp++)
#pragma unroll
                    for (int hh = 0; hh < 2; hh++) {
                        float* c = accv[fm][fp * 2 + hh];
                        asm volatile(
                            "mma.sync.aligned.m16n8k16.row.col.f32.f16.f16.f32 "
                            "{%0,%1,%2,%3}, {%4,%5,%6,%7}, {%8,%9}, {%0,%1,%2,%3};\n"
                            : "+f"(c[0]), "+f"(c[1]), "+f"(c[2]), "+f"(c[3])
                            : "r"(a[fm][0]), "r"(a[fm][1]), "r"(a[fm][2]), "r"(a[fm][3]),
                              "r"(bf[fp][hh * 2]), "r"(bf[fp][hh * 2 + 1]));
                    }
        }
    };

    loadStage(0, 0);
    loadStage(1, 1);
    loadStage(2, 2);

    for (int kt = 0; kt < NKT; ++kt) {
        asm volatile("cp.async.wait_group 2;\n");
        __syncthreads();
        if (kt + 3 < NKT) loadStage(kt + 3, (kt + 3) % NSTG);
        else asm volatile("cp.async.commit_group;\n");
        compute(kt % NSTG);
    }

    __syncthreads();
#pragma unroll
    for (int ci = 0; ci < 4; ci++) {
        if (wn == (ci >> 1)) {
            const int fbase = (ci & 1) * 4;
#pragma unroll
            for (int fm = 0; fm < 2; fm++)
#pragma unroll
                for (int f = 0; f < 4; f++) {
                    int fn = fbase + f;
#pragma unroll
                    for (int e = 0; e < 4; e++) {
                        int row = wm * 32 + fm * 16 + (lane >> 2) + (e >> 1) * 8;
                        int col = f * 8 + 2 * (lane & 3) + (e & 1);
                        Ep[row * 33 + col] = accv[fm][fn][e];
                    }
                }
        }
        __syncthreads();
        for (int idx = tid; idx < 32 * 128; idx += 256) {
            int ol = idx >> 7, m = idx & 127;
            int o = o0 + ci * 32 + ol;
            float v = Ep[m * 33 + ol] + bias[o];
            out[(((size_t)(b * OC_ + o)) << 12) + p0 + m] = fmaxf(v, 0.0f);
        }
        __syncthreads();
    }
}

// ============================================================
extern "C" void kernel_launch(void* const* d_in, const int* in_sizes, int n_in,
                              void* d_out, int out_size) {
    const float* feat = (const float*)d_in[0];
    const float* w    = (const float*)d_in[1];
    const float* bias = (const float*)d_in[2];
    float* out = (float*)d_out;

    static bool attr_set = false;
    if (!attr_set) {
        cudaFuncSetAttribute(gemm_kernel, cudaFuncAttributeMaxDynamicSharedMemorySize,
                             GEMM_SMEM);
        attr_set = true;
    }

    corr_kernel<<<dim3(2, 2, B_ * NG), 256>>>(feat);            // launch 1
    fuse_kernel<<<(OC_ * KTOT + 255) / 256, 256>>>(w);          // launch 2 (convW + inv)
    combine_kernel<<<(B_ * 32 * HW_) / 256, 256>>>();           // launch 3
    gemm_kernel<<<dim3(8, 32, B_), 256, GEMM_SMEM>>>(bias, out); // launch 4 (captured)
}

// round 8
// speedup vs baseline: 1.5425x; 1.0054x over previous
#include <cuda_runtime.h>
#include <cuda_fp16.h>
#include <cstdint>
#include <math.h>

// feature: [8,1024,64,64] f32 ; conv_w: [1024,1049] ; conv_b: [1024] ; out f32 same shape
// cat channels: 0..1023 feature, 1024..1048 corr (j = cc*5+r), padded to 1088.

#define B_      8
#define C_      1024
#define HW_     4096
#define OC_     1024
#define KTOT    1088      // 17 * 64
#define KREAL   1049
#define NG      8

// ---------------- scratch ----------------
__device__ __half g_Wh[OC_ * KTOT];                          // fp16 weights, zero-padded
__device__ __half g_Ah[(size_t)B_ * KTOT * HW_];             // fp16 A [b][1088][4096]; 1056..1087 stay 0
__device__ __align__(16) float g_sspart[NG * B_ * HW_];
__device__ __align__(16) float g_inv[B_ * HW_];
__device__ __align__(16) float g_accpart[(size_t)NG * B_ * 25 * HW_];

// ---------------- f32x2 helpers ----------------
typedef unsigned long long u64t;
__device__ __forceinline__ u64t pk2(float a, float b) {
    u64t r; asm("mov.b64 %0, {%1, %2};" : "=l"(r) : "f"(a), "f"(b)); return r;
}
__device__ __forceinline__ void fma2(u64t& d, u64t a, u64t b) {
    asm("fma.rn.f32x2 %0, %1, %2, %0;" : "+l"(d) : "l"(a), "l"(b));
}
__device__ __forceinline__ float2 up2(u64t a) {
    float2 r; asm("mov.b64 {%0, %1}, %2;" : "=f"(r.x), "=f"(r.y) : "l"(a)); return r;
}

// ============================================================
// fused: convW (conv_w -> fp16 padded) + inv (1/max(||f||,eps))
// ============================================================
__global__ void fuse_kernel(const float* __restrict__ w) {
    int idx = blockIdx.x * 256 + threadIdx.x;
    if (idx < OC_ * KTOT) {
        int o = idx / KTOT, k = idx - o * KTOT;
        float v = (k < KREAL) ? w[o * KREAL + k] : 0.0f;
        g_Wh[idx] = __float2half(v);
    }
    if (idx < B_ * HW_) {
        float ssv = 0.0f;
#pragma unroll
        for (int g = 0; g < NG; g++) ssv += g_sspart[g * B_ * HW_ + idx];
        g_inv[idx] = 1.0f / fmaxf(sqrtf(ssv), 1e-12f);
    }
}

// ============================================================
// corr partials + sumsq + fp16 feature write.
// 32x32 tile, 2x2 px/thread, f32x2 FMA, NG=8 groups of 128 ch.
// ============================================================
__global__ __launch_bounds__(256, 2) void corr_kernel(const float* __restrict__ feat) {
    __shared__ float tile[2][4][36 * 40];

    const int tid = threadIdx.x;
    const int tx = tid & 15, ty = tid >> 4;
    const int x0 = blockIdx.x * 32, y0 = blockIdx.y * 32;
    const int b = blockIdx.z >> 3, g = blockIdx.z & 7;
    const float* fb = feat + (size_t)b * C_ * HW_;
    __half* ah = g_Ah + ((size_t)b * KTOT << 12);
    const int cbase = g * 128;

    u64t acc2[25][2];
    u64t ss2[2];
#pragma unroll
    for (int j = 0; j < 25; j++) { acc2[j][0] = 0ull; acc2[j][1] = 0ull; }
    ss2[0] = 0ull; ss2[1] = 0ull;

    auto load4 = [&](int c0, int buf) {
#pragma unroll 2
        for (int u = tid; u < 1440; u += 256) {
            int cc = u / 360, pos = u - cc * 360;
            int j = pos / 10, i = pos - j * 10;
            int gy = y0 - 2 + j;
            int gx0 = x0 - 4 + i * 4;
            bool valid = ((unsigned)gy < 64u) && ((unsigned)gx0 < 64u);
            const float* src = fb + (size_t)(c0 + cc) * HW_ + (valid ? (gy * 64 + gx0) : 0);
            unsigned dst = (unsigned)__cvta_generic_to_shared(&tile[buf][cc][j * 40 + i * 4]);
            int sz = valid ? 16 : 0;
            asm volatile("cp.async.ca.shared.global [%0], [%1], 16, %2;\n"
                         :: "r"(dst), "l"(src), "r"(sz));
        }
    };

    load4(cbase, 0);
    asm volatile("cp.async.commit_group;\n");

    for (int it = 0; it < 32; ++it) {
        if (it < 31) {
            load4(cbase + (it + 1) * 4, (it + 1) & 1);
            asm volatile("cp.async.commit_group;\n");
            asm volatile("cp.async.wait_group 1;\n");
        } else {
            asm volatile("cp.async.wait_group 0;\n");
        }
        __syncthreads();
        const int cb = it & 1;
#pragma unroll
        for (int q = 0; q < 4; q++) {
            const float* tq = &tile[cb][q][0];
            const int c = cbase + it * 4 + q;
            u64t cen2[2];
#pragma unroll
            for (int yy = 0; yy < 2; yy++) {
                float2 cf = *(const float2*)&tq[(2 * ty + yy + 2) * 40 + 2 * tx + 4];
                cen2[yy] = pk2(cf.x, cf.y);
                fma2(ss2[yy], cen2[yy], cen2[yy]);
                __half2 hv = __floats2half2_rn(cf.x, cf.y);
                *(__half2*)&ah[((size_t)c << 12) + (y0 + 2 * ty + yy) * 64 + x0 + 2 * tx] = hv;
            }
#pragma unroll
            for (int rr = 0; rr < 6; rr++) {
                const float* rp = &tq[(2 * ty + rr) * 40 + 2 * tx + 2];
                float2 p0 = *(const float2*)(rp);
                float2 p1 = *(const float2*)(rp + 2);
                float2 p2 = *(const float2*)(rp + 4);
                u64t t[5];
                t[0] = pk2(p0.x, p0.y);
                t[1] = pk2(p0.y, p1.x);
                t[2] = pk2(p1.x, p1.y);
                t[3] = pk2(p1.y, p2.x);
                t[4] = pk2(p2.x, p2.y);
#pragma unroll
                for (int cc = 0; cc < 5; cc++) {
                    if (rr <= 4) fma2(acc2[cc * 5 + rr][0], t[cc], cen2[0]);
                    if (rr >= 1) fma2(acc2[cc * 5 + rr - 1][1], t[cc], cen2[1]);
                }
            }
        }
        __syncthreads();
    }

#pragma unroll
    for (int yy = 0; yy < 2; yy++) {
        int p = (y0 + 2 * ty + yy) * 64 + x0 + 2 * tx;
        *(float2*)&g_sspart[(g * B_ + b) * HW_ + p] = up2(ss2[yy]);
#pragma unroll
        for (int j = 0; j < 25; j++)
            *(float2*)&g_accpart[((size_t)(g * B_ + b) * 25 + j) * HW_ + p] = up2(acc2[j][yy]);
    }
}

// ============================================================
// combine: normalized corr -> fp16 A channels 1024..1087 (zeros beyond 25)
// ============================================================
__global__ void combine_kernel() {
    int idx = blockIdx.x * 256 + threadIdx.x;     // B_*64*HW_
    if (idx >= B_ * 64 * HW_) return;
    int p = idx & (HW_ - 1);
    int j = (idx >> 12) & 63;
    int b = idx >> 18;
    float v = 0.0f;
    if (j < 25) {
        int y = p >> 6, x = p & 63;
        int ccs = j / 5, r = j - ccs * 5;
        int tyy = y + r - 2, txx = x + ccs - 2;
        if ((unsigned)tyy < 64u && (unsigned)txx < 64u) {
            float a = 0.0f;
#pragma unroll
            for (int g = 0; g < NG; g++)
                a += g_accpart[((size_t)(g * B_ + b) * 25 + j) * HW_ + p];
            v = a * g_inv[b * HW_ + p] * g_inv[b * HW_ + tyy * 64 + txx];
        }
    }
    g_Ah[((size_t)(b * KTOT + C_ + j) << 12) + p] = __float2half(v);
}

// ============================================================
// GEMM  out[b,o,p] = relu( sum_k Wh[o,k]*Ah[b,k,p] + bias[o] )
// CTA tile 128p x 128o x 64k, 256 threads, 3-stage cp.async (k64 stages), 2 CTAs/SM.
// ============================================================
#define NKT 17
#define A_STAGE 17408       // 64*136*2
#define B_STAGE 18432       // 128*72*2
#define NSTG 3
#define GEMM_SMEM (NSTG * (A_STAGE + B_STAGE))

__global__ __launch_bounds__(256, 2) void gemm_kernel(const float* __restrict__ bias,
                                                      float* __restrict__ out) {
    extern __shared__ __align__(16) unsigned char SM[];
    __half* As[NSTG];
    __half* Bs[NSTG];
#pragma unroll
    for (int s = 0; s < NSTG; s++) {
        As[s] = (__half*)(SM + s * (A_STAGE + B_STAGE));
        Bs[s] = (__half*)(SM + s * (A_STAGE + B_STAGE) + A_STAGE);
    }
    float* Ep = (float*)SM;   // [128][33] epilogue staging

    const int tid = threadIdx.x;
    const int lane = tid & 31, wid = tid >> 5;
    const int wm = wid & 3, wn = wid >> 2;
    const int o0 = blockIdx.x * 128;
    const int p0 = blockIdx.y * 128;
    const int b  = blockIdx.z;

    const __half* aBase = g_Ah + ((size_t)b * KTOT << 12) + p0;

    float accv[2][8][4];
#pragma unroll
    for (int i = 0; i < 2; i++)
#pragma unroll
        for (int j = 0; j < 8; j++)
#pragma unroll
            for (int e = 0; e < 4; e++) accv[i][j][e] = 0.0f;

    auto loadStage = [&](int kt, int buf) {
        // A: [k 64][m 128] fp16 -> 1024 16B chunks
#pragma unroll
        for (int s = 0; s < 4; s++) {
            int u = tid + s * 256;
            int row = u >> 4, ch = u & 15;
            const __half* src = aBase + (((size_t)(kt * 64 + row)) << 12) + ch * 8;
            unsigned dst = (unsigned)__cvta_generic_to_shared(As[buf] + row * 136 + ch * 8);
            asm volatile("cp.async.cg.shared.global [%0], [%1], 16;\n" :: "r"(dst), "l"(src));
        }
        // B: [n 128][k 64] fp16 -> 1024 16B chunks
#pragma unroll
        for (int s = 0; s < 4; s++) {
            int u = tid + s * 256;
            int orow = u >> 3, q = u & 7;
            const __half* src = g_Wh + (size_t)(o0 + orow) * KTOT + kt * 64 + q * 8;
            unsigned dst = (unsigned)__cvta_generic_to_shared(Bs[buf] + orow * 72 + q * 8);
            asm volatile("cp.async.cg.shared.global [%0], [%1], 16;\n" :: "r"(dst), "l"(src));
        }
        asm volatile("cp.async.commit_group;\n");
    };

    auto compute = [&](int buf) {
#pragma unroll
        for (int ks = 0; ks < 4; ks++) {
            const int kb = ks * 16;
            unsigned a[2][4];
#pragma unroll
            for (int fm = 0; fm < 2; fm++) {
                int kk = kb + ((lane >> 4) & 1) * 8 + (lane & 7);
                int mm = wm * 32 + fm * 16 + ((lane >> 3) & 1) * 8;
                unsigned addr = (unsigned)__cvta_generic_to_shared(As[buf] + kk * 136 + mm);
                asm volatile("ldmatrix.sync.aligned.m8n8.x4.trans.shared.b16 {%0,%1,%2,%3}, [%4];\n"
                             : "=r"(a[fm][0]), "=r"(a[fm][1]), "=r"(a[fm][2]), "=r"(a[fm][3])
                             : "r"(addr));
            }
            unsigned bf[4][4];
#pragma unroll
            for (int fp = 0; fp < 4; fp++) {
                int row = wn * 64 + fp * 16 + (lane & 7) + ((lane >> 4) & 1) * 8;
                int kcol = kb + ((lane >> 3) & 1) * 8;
                unsigned addr = (unsigned)__cvta_generic_to_shared(Bs[buf] + row * 72 + kcol);
                asm volatile("ldmatrix.sync.aligned.m8n8.x4.shared.b16 {%0,%1,%2,%3}, [%4];\n"
                             : "=r"(bf[fp][0]), "=r"(bf[fp][1]), "=r"(bf[fp][2]), "=r"(bf[fp][3])
                             : "r"(addr));
            }
#pragma unroll
            for (int fm = 0; fm < 2; fm++)
#pragma unroll
                for (int fp = 0; fp < 4; fp++)
#pragma unroll
                    for (int hh = 0; hh < 2; hh++) {
                        float* c = accv[fm][fp * 2 + hh];
                        asm volatile(
                            "mma.sync.aligned.m16n8k16.row.col.f32.f16.f16.f32 "
                            "{%0,%1,%2,%3}, {%4,%5,%6,%7}, {%8,%9}, {%0,%1,%2,%3};\n"
                            : "+f"(c[0]), "+f"(c[1]), "+f"(c[2]), "+f"(c[3])
                            : "r"(a[fm][0]), "r"(a[fm][1]), "r"(a[fm][2]), "r"(a[fm][3]),
                              "r"(bf[fp][hh * 2]), "r"(bf[fp][hh * 2 + 1]));
                    }
        }
    };

    loadStage(0, 0);
    loadStage(1, 1);

    for (int kt = 0; kt < NKT; ++kt) {
        asm volatile("cp.async.wait_group 1;\n");
        __syncthreads();
        if (kt + 2 < NKT) loadStage(kt + 2, (kt + 2) % NSTG);
        else asm volatile("cp.async.commit_group;\n");
        compute(kt % NSTG);
    }

    __syncthreads();
#pragma unroll
    for (int ci = 0; ci < 4; ci++) {
        if (wn == (ci >> 1)) {
            const int fbase = (ci & 1) * 4;
#pragma unroll
            for (int fm = 0; fm < 2; fm++)
#pragma unroll
                for (int f = 0; f < 4; f++) {
                    int fn = fbase + f;
#pragma unroll
                    for (int e = 0; e < 4; e++) {
                        int row = wm * 32 + fm * 16 + (lane >> 2) + (e >> 1) * 8;
                        int col = f * 8 + 2 * (lane & 3) + (e & 1);
                        Ep[row * 33 + col] = accv[fm][fn][e];
                    }
                }
        }
        __syncthreads();
        for (int idx = tid; idx < 32 * 128; idx += 256) {
            int ol = idx >> 7, m = idx & 127;
            int o = o0 + ci * 32 + ol;
            float v = Ep[m * 33 + ol] + bias[o];
            out[(((size_t)(b * OC_ + o)) << 12) + p0 + m] = fmaxf(v, 0.0f);
        }
        __syncthreads();
    }
}

// ============================================================
extern "C" void kernel_launch(void* const* d_in, const int* in_sizes, int n_in,
                              void* d_out, int out_size) {
    const float* feat = (const float*)d_in[0];
    const float* w    = (const float*)d_in[1];
    const float* bias = (const float*)d_in[2];
    float* out = (float*)d_out;

    static bool attr_set = false;
    if (!attr_set) {
        cudaFuncSetAttribute(gemm_kernel, cudaFuncAttributeMaxDynamicSharedMemorySize,
                             GEMM_SMEM);
        attr_set = true;
    }

    corr_kernel<<<dim3(2, 2, B_ * NG), 256>>>(feat);              // launch 1
    fuse_kernel<<<(OC_ * KTOT + 255) / 256, 256>>>(w);            // launch 2
    combine_kernel<<<(B_ * 64 * HW_) / 256, 256>>>();             // launch 3
    gemm_kernel<<<dim3(8, 32, B_), 256, GEMM_SMEM>>>(bias, out);  // launch 4 (captured)
}